// round 16
// baseline (speedup 1.0000x reference)
#include <cuda_runtime.h>

#define BB 8
#define CC 32
#define HH 64
#define VOCABN 4096
#define NELEM (BB*CC*HH*HH)   // 131072
#define NSCALE 7
#define NKEYS 43688           // sum of B*pn*pn over all scales

typedef unsigned long long ull;

// -------- scratch (static __device__, no allocations) --------
__device__ float g_cbn[VOCABN*CC];            // normalized codebook, PAIR-INTERLEAVED:
                                              // g_cbn[p*64 + 2*c + h] = cbn[2p+h][c]
__device__ float g_frest[NELEM];              // running residual
__device__ float g_rest[BB*CC*32*32];         // downsampled residual (pn=8..32)
__device__ ull g_keys[NKEYS];                 // packed (sim,idx) keys, per-scale offsets
__device__ float g_partials[NSCALE*128];      // per-block loss partials

// -------- f32x2 packed math (sm_100+) --------
__device__ __forceinline__ ull fma2(ull a, ull b, ull c) {
    ull d; asm("fma.rn.f32x2 %0, %1, %2, %3;" : "=l"(d) : "l"(a), "l"(b), "l"(c)); return d;
}
__device__ __forceinline__ ull add2(ull a, ull b) {
    ull d; asm("add.rn.f32x2 %0, %1, %2;" : "=l"(d) : "l"(a), "l"(b)); return d;
}
__device__ __forceinline__ ull pack2(float lo, float hi) {
    ull d; asm("mov.b64 %0, {%1, %2};" : "=l"(d) : "f"(lo), "f"(hi)); return d;
}
__device__ __forceinline__ void unpack2(ull v, float& lo, float& hi) {
    asm("mov.b64 {%0, %1}, %2;" : "=f"(lo), "=f"(hi) : "l"(v));
}

__device__ __forceinline__ unsigned f2ord(float f) {
    unsigned u = __float_as_uint(f);
    return (u & 0x80000000u) ? ~u : (u | 0x80000000u);
}
__device__ __forceinline__ int key_idx(ull key) {
    return (int)(0xFFFFFFFFu - (unsigned)(key & 0xFFFFFFFFull));
}

// -------- codebook row-normalize -> pair-interleaved layout --------
__global__ void k_cbn(const float* __restrict__ cb) {
    int row = (blockIdx.x*blockDim.x + threadIdx.x) >> 5;
    int lane = threadIdx.x & 31;
    if (row >= VOCABN) return;
    float v = cb[row*CC + lane];
    float s = v*v;
    #pragma unroll
    for (int o = 16; o; o >>= 1) s += __shfl_xor_sync(0xffffffffu, s, o);
    int p = row >> 1, h = row & 1;
    g_cbn[p*64 + 2*lane + h] = v / sqrtf(s);
}

// -------- area downsample, thread per output (k <= 4) --------
__global__ void k_ds_thread(const float* __restrict__ src, int pn, int k) {
    int i = blockIdx.x*blockDim.x + threadIdx.x;
    int total = BB*CC*pn*pn;
    if (i >= total) return;
    int q = i % pn; int p = (i/pn) % pn; int bc = i/(pn*pn);
    const float* s = src + bc*HH*HH + p*k*HH + q*k;
    float acc = 0.f;
    for (int yy = 0; yy < k; yy++)
        for (int xx = 0; xx < k; xx++) acc += s[yy*HH + xx];
    g_rest[i] = acc * (1.f/(float)(k*k));
}

// -------- area downsample, warp per output (k >= 8) --------
__global__ void k_ds_warp(const float* __restrict__ src, int pn, int k) {
    int gw = (blockIdx.x*blockDim.x + threadIdx.x) >> 5;
    int lane = threadIdx.x & 31;
    int total = BB*CC*pn*pn;
    if (gw >= total) return;
    int q = gw % pn; int p = (gw/pn) % pn; int bc = gw/(pn*pn);
    const float* s = src + bc*HH*HH + p*k*HH + q*k;
    int kk = k*k;
    float acc = 0.f;
    for (int t = lane; t < kk; t += 32) acc += s[(t/k)*HH + (t % k)];
    #pragma unroll
    for (int o = 16; o; o >>= 1) acc += __shfl_xor_sync(0xffffffffu, acc, o);
    if (lane == 0) g_rest[gw] = acc * (1.f/(float)kk);
}

// -------- pair dot-product core: 32 channels vs packed code pair --------
__device__ __forceinline__ void pair_sim(const ull* __restrict__ vd,
                                         const float* __restrict__ pairrow,
                                         float& lo, float& hi) {
    const ulonglong2* row2 = (const ulonglong2*)pairrow;
    ull a0 = 0ull, a1 = 0ull, a2 = 0ull, a3 = 0ull;
    #pragma unroll
    for (int cc = 0; cc < 8; cc++) {
        ulonglong2 r0 = row2[2*cc];
        ulonglong2 r1 = row2[2*cc+1];
        a0 = fma2(vd[4*cc+0], r0.x, a0);
        a1 = fma2(vd[4*cc+1], r0.y, a1);
        a2 = fma2(vd[4*cc+2], r1.x, a2);
        a3 = fma2(vd[4*cc+3], r1.y, a3);
    }
    ull s = add2(add2(a0, a1), add2(a2, a3));
    unpack2(s, lo, hi);
}

// -------- argmax with FUSED area-downsample, block per vector (pn<=4) --------
__global__ void k_argmax_small(const float* __restrict__ src, int pn, int k, int koff) {
    __shared__ float psum[512];
    __shared__ float vsh[CC];
    __shared__ ull kred[512];
    int n = blockIdx.x;
    int tid = threadIdx.x;
    int pnpn = pn*pn;
    int b = n / pnpn, r = n % pnpn;
    int p = r / pn, q = r % pn;
    // fused patch mean: channel c = tid>>4, 16 partial-sum threads per channel
    {
        int c = tid >> 4, sub = tid & 15;
        const float* sp = src + (b*CC + c)*HH*HH + p*k*HH + q*k;
        int kk = k*k;
        float a = 0.f;
        for (int t = sub; t < kk; t += 16) a += sp[(t/k)*HH + (t%k)];
        psum[tid] = a;
        __syncthreads();
        if (sub == 0) {
            float s = 0.f;
            #pragma unroll
            for (int u = 0; u < 16; u++) s += psum[(c<<4) + u];
            vsh[c] = s * (1.f/(float)kk);
        }
        __syncthreads();
    }
    ull vd[CC];
    #pragma unroll
    for (int c = 0; c < CC; c++) { float v = vsh[c]; vd[c] = pack2(v, v); }
    float best = -1e30f; int bidx = 0;
    for (int pr = tid; pr < VOCABN/2; pr += 512) {
        float lo, hi;
        pair_sim(vd, g_cbn + pr*64, lo, hi);
        if (lo > best) { best = lo; bidx = 2*pr; }
        if (hi > best) { best = hi; bidx = 2*pr + 1; }
    }
    kred[tid] = ((ull)f2ord(best) << 32) | (ull)(0xFFFFFFFFu - (unsigned)bidx);
    __syncthreads();
    #pragma unroll
    for (int s = 256; s > 0; s >>= 1) {
        if (tid < s) { ull o = kred[tid+s]; if (o > kred[tid]) kred[tid] = o; }
        __syncthreads();
    }
    if (tid == 0) g_keys[koff + n] = kred[0];
}

// -------- argmax, thread per vector, codes split across blockIdx.y --------
// REQUIREMENT: chunk must be a multiple of 256 (full tiles only).
__global__ void k_argmax_big(const float* __restrict__ rest, int N, int pnpn,
                             int chunk, int koff) {
    __shared__ float scb[256*CC];  // 32 KB tile: 128 pairs x 64 floats
    int n = blockIdx.x*128 + threadIdx.x;
    int c0 = blockIdx.y * chunk;
    ull vd[CC];
    bool active = (n < N);
    if (active) {
        int b = n / pnpn, r = n % pnpn;
        const float* s = rest + b*CC*pnpn + r;
        #pragma unroll
        for (int c = 0; c < CC; c++) { float v = s[c*pnpn]; vd[c] = pack2(v, v); }
    } else {
        #pragma unroll
        for (int c = 0; c < CC; c++) vd[c] = 0ull;
    }
    float best = -1e30f; int bidx = 0;
    for (int t0 = 0; t0 < chunk; t0 += 256) {
        __syncthreads();
        const float4* src4 = (const float4*)(g_cbn + (c0 + t0)*CC);
        float4* dst4 = (float4*)scb;
        #pragma unroll 4
        for (int i = threadIdx.x; i < 256*8; i += 128) dst4[i] = src4[i];
        __syncthreads();
        #pragma unroll 4
        for (int j2 = 0; j2 < 128; j2++) {
            float lo, hi;
            pair_sim(vd, scb + j2*64, lo, hi);
            int code = c0 + t0 + 2*j2;
            if (lo > best) { best = lo; bidx = code; }
            if (hi > best) { best = hi; bidx = code + 1; }
        }
    }
    if (active) {
        ull key = ((ull)f2ord(best) << 32) | (ull)(0xFFFFFFFFu - (unsigned)bidx);
        atomicMax(g_keys + koff + n, key);
    }
}

// -------- bicubic weight (PyTorch A=-0.75) --------
__device__ __forceinline__ float cubicw(float t) {
    t = fabsf(t);
    float t2 = t*t, t3 = t2*t;
    if (t <= 1.f) return 1.25f*t3 - 2.25f*t2 + 1.f;
    if (t < 2.f)  return -0.75f*t3 + 3.75f*t2 - 6.f*t + 3.f;
    return 0.f;
}

// -------- FUSED gather/bicubic-upsample + conv3x3 + Phi + update + loss ----
// Phase A builds the 32ic x 6 x 66 halo tile directly from g_keys + codebook
// (replaces the separate k_up kernel and the g_hup round-trip).
// Phase B: WARP-PER-OC-PAIR conv as in r15 (py-split, float2 taps).
// grid (16 ytiles, 8 b) = 128 blocks, flat 512 threads, ~96KB smem.
#define CONV_SMEM ((32*6*66 + 16*32*10*2 + 32 + 512 + 64*4 + 64*4 + 6*4 + 6*4)*4)

__global__ __launch_bounds__(512, 1) void k_upconv(
        const float* __restrict__ f, const float* __restrict__ cb,
        const float* __restrict__ phi_w, const float* __restrict__ phi_b,
        float* __restrict__ fhat, int kphi, int si, int pn, int koff) {
    extern __shared__ float sh[];
    float* tile  = sh;                    // 12672
    float* wsh2f = tile + 32*6*66;        // 10240
    float* bsh   = wsh2f + 16*32*10*2;    // 32
    float* red   = bsh + 32;              // 512
    float* wxA   = red + 512;             // [64][4]
    int*   pxA   = (int*)(wxA + 64*4);    // [64][4]
    float* wyA   = (float*)(pxA + 64*4);  // [6][4]
    int*   pyA   = (int*)(wyA + 6*4);     // [6][4]
    int tid = threadIdx.x;                // 0..511 (flat block)
    int P    = tid >> 5;                  // warp id = oc-pair 0..15
    int lane = tid & 31;
    int r = lane >> 4;                    // row-pair within 4-row stripe
    int q = lane & 15;                    // col quad
    int y0 = blockIdx.x*4;
    int b  = blockIdx.y;
    const ull* keys = g_keys + koff;

    // weight interleave (as r15)
    const float* wsrc = phi_w + (size_t)(kphi*32)*32*9;
    for (int i = tid; i < 16*32*9; i += 512) {
        int Pp = i / 288; int rem = i % 288;
        int ic = rem / 9; int t = rem % 9;
        int dst = ((Pp*32 + ic)*10 + t)*2;
        wsh2f[dst]     = wsrc[(2*Pp)*288 + rem];
        wsh2f[dst + 1] = wsrc[(2*Pp + 1)*288 + rem];
    }
    if (tid < 32) bsh[tid] = phi_b[kphi*32 + tid];

    // ---- Phase A: build tile from keys ----
    if (pn == HH) {
        for (int v = tid; v < 32*6*66; v += 512) {
            int xx = v % 66; int yy = (v/66) % 6; int ic = v/(66*6);
            int gy = y0 - 1 + yy, gx = xx - 1;
            float val = 0.f;
            if ((unsigned)gy < 64u && (unsigned)gx < 64u) {
                int idx = key_idx(keys[(b*HH + gy)*HH + gx]);
                val = cb[idx*CC + ic];
            }
            tile[v] = val;
        }
    } else {
        // bicubic weights: threads 0..63 -> X positions, 64..69 -> the 6 gy rows
        if (tid < 70) {
            float scale = (float)pn / (float)HH;
            bool isx = tid < 64;
            int pos = isx ? tid : (y0 - 1 + (tid - 64));
            if (isx || (unsigned)pos < 64u) {
                float fz = (pos + 0.5f)*scale - 0.5f;
                int z0 = (int)floorf(fz);
                #pragma unroll
                for (int t = 0; t < 4; t++) {
                    float w = cubicw(fz - (float)(z0 - 1 + t));
                    int pz = min(max(z0 - 1 + t, 0), pn - 1);
                    if (isx) { wxA[tid*4 + t] = w; pxA[tid*4 + t] = pz; }
                    else     { wyA[(tid-64)*4 + t] = w; pyA[(tid-64)*4 + t] = pz; }
                }
            }
        }
        __syncthreads();
        int nb = b*pn*pn;
        for (int v = tid; v < 32*6*66; v += 512) {
            int xx = v % 66; int yy = (v/66) % 6; int ic = v/(66*6);
            int gy = y0 - 1 + yy, gx = xx - 1;
            float val = 0.f;
            if ((unsigned)gy < 64u && (unsigned)gx < 64u) {
                float vals[16];
                #pragma unroll
                for (int t = 0; t < 16; t++) {
                    int py = pyA[yy*4 + (t >> 2)], px = pxA[gx*4 + (t & 3)];
                    int idx = key_idx(keys[nb + py*pn + px]);
                    vals[t] = cb[idx*CC + ic];
                }
                float acc = 0.f;
                #pragma unroll
                for (int t2 = 0; t2 < 4; t2++) {
                    float rowacc = vals[t2*4+0]*wxA[gx*4+0] + vals[t2*4+1]*wxA[gx*4+1]
                                 + vals[t2*4+2]*wxA[gx*4+2] + vals[t2*4+3]*wxA[gx*4+3];
                    acc += wyA[yy*4 + t2]*rowacc;
                }
                val = acc;
            }
            tile[v] = val;
        }
    }
    __syncthreads();

    // ---- Phase B: conv (identical to r15) ----
    const ull* wsh2 = (const ull*)wsh2f;
    ull acc2[8];
    #pragma unroll
    for (int i = 0; i < 8; i++) acc2[i] = 0ull;

    for (int ic = 0; ic < 32; ic++) {
        const ull* w = wsh2 + (P*32 + ic)*10;
        ulonglong2 w01 = *(const ulonglong2*)(w);
        ulonglong2 w23 = *(const ulonglong2*)(w + 2);
        ulonglong2 w45 = *(const ulonglong2*)(w + 4);
        ulonglong2 w67 = *(const ulonglong2*)(w + 6);
        ull w8 = w[8];
        #pragma unroll
        for (int py = 0; py < 2; py++) {
            const float2* tb2 = (const float2*)(tile + (ic*6 + 2*r + py)*66 + 4*q);
            ull t[3][6];
            #pragma unroll
            for (int yy = 0; yy < 3; yy++) {
                float2 f0 = tb2[yy*33 + 0];
                float2 f1 = tb2[yy*33 + 1];
                float2 f2 = tb2[yy*33 + 2];
                t[yy][0] = pack2(f0.x, f0.x); t[yy][1] = pack2(f0.y, f0.y);
                t[yy][2] = pack2(f1.x, f1.x); t[yy][3] = pack2(f1.y, f1.y);
                t[yy][4] = pack2(f2.x, f2.x); t[yy][5] = pack2(f2.y, f2.y);
            }
            #pragma unroll
            for (int px = 0; px < 4; px++) {
                ull a = acc2[py*4 + px];
                a = fma2(t[0][px+0], w01.x, a);
                a = fma2(t[0][px+1], w01.y, a);
                a = fma2(t[0][px+2], w23.x, a);
                a = fma2(t[1][px+0], w23.y, a);
                a = fma2(t[1][px+1], w45.x, a);
                a = fma2(t[1][px+2], w45.y, a);
                a = fma2(t[2][px+0], w67.x, a);
                a = fma2(t[2][px+1], w67.y, a);
                a = fma2(t[2][px+2], w8,    a);
                acc2[py*4 + px] = a;
            }
        }
    }

    float ss = 0.f;
    #pragma unroll
    for (int py = 0; py < 2; py++) {
        int yrow = 2*r + py;
        int y = y0 + yrow;
        #pragma unroll
        for (int px = 0; px < 4; px++) {
            int x = 4*q + px;
            float aLo, aHi;
            unpack2(acc2[py*4 + px], aLo, aHi);
            #pragma unroll
            for (int hh = 0; hh < 2; hh++) {
                int oc = 2*P + hh;
                float a = hh ? aHi : aLo;
                float hid = tile[(oc*6 + yrow + 1)*66 + (x + 1)];
                float hp = 0.5f*hid + 0.5f*(a + bsh[oc]);
                int gi = ((b*CC + oc)*HH + y)*HH + x;
                float fv = f[gi];
                float fh = (si == 0 ? 0.f : fhat[gi]) + hp;
                fhat[gi] = fh;
                g_frest[gi] = fv - fh;
                float d = fh - fv;
                ss += d*d;
            }
        }
    }

    red[tid] = ss;
    __syncthreads();
    #pragma unroll
    for (int s = 256; s > 0; s >>= 1) {
        if (tid < s) red[tid] += red[tid + s];
        __syncthreads();
    }
    if (tid == 0) {
        int bl = blockIdx.y*16 + blockIdx.x;   // 0..127
        g_partials[si*128 + bl] = red[0];
    }
}

// -------- final loss reduce (deterministic fixed order) --------
__global__ void k_final(float* __restrict__ out) {
    __shared__ float red[128];
    int tid = threadIdx.x;
    float s = 0.f;
    for (int i = tid; i < NSCALE*128; i += 128) s += g_partials[i];
    red[tid] = s;
    __syncthreads();
    #pragma unroll
    for (int st = 64; st > 0; st >>= 1) {
        if (tid < st) red[tid] += red[tid + st];
        __syncthreads();
    }
    if (tid == 0) {
        float T = red[0];
        out[NELEM]     = T / (7.f * (float)NELEM);
        out[NELEM + 1] = 0.25f * T / (float)NELEM;
    }
}

// -------- host --------
extern "C" void kernel_launch(void* const* d_in, const int* in_sizes, int n_in,
                              void* d_out, int out_size) {
    const float* f    = (const float*)d_in[0];
    const float* cb   = (const float*)d_in[1];
    const float* phiw = (const float*)d_in[2];
    const float* phib = (const float*)d_in[3];
    float* out = (float*)d_out;

    cudaFuncSetAttribute(k_upconv, cudaFuncAttributeMaxDynamicSharedMemorySize, CONV_SMEM);

    void *keysPtr = nullptr, *frestPtr = nullptr, *restPtr = nullptr;
    cudaGetSymbolAddress(&keysPtr, g_keys);
    cudaGetSymbolAddress(&frestPtr, g_frest);
    cudaGetSymbolAddress(&restPtr, g_rest);

    // one upfront zero of the whole key buffer (covers all chunked-atomic scales)
    cudaMemsetAsync(keysPtr, 0, (size_t)NKEYS*sizeof(ull));
    k_cbn<<<(VOCABN*32 + 255)/256, 256>>>(cb);

    const int pns[NSCALE]    = {1, 2, 4, 8, 16, 32, 64};
    // PHI ticks in float64: si=3 (key 0.5) resolves to phi index 2 (fp tie-break), NOT 1.
    const int phiIdx[NSCALE] = {0, 0, 1, 2, 2, 3, 3};
    // chunks MUST be multiples of 256 (k_argmax_big scans full 256-code tiles).
    const int chunks[NSCALE] = {0, 0, 0, 256, 256, 512, 2048};
    // per-scale key offsets: prefix sums of N = 8*pn*pn
    const int koffs[NSCALE]  = {0, 8, 40, 168, 680, 2728, 10920};

    for (int si = 0; si < NSCALE; si++) {
        int pn = pns[si]; int pnpn = pn*pn; int N = BB*pnpn; int k = HH/pn;
        const float* src = (si == 0) ? f : (const float*)frestPtr;

        if (pn <= 4) {
            // fused downsample + argmax, block per vector
            k_argmax_small<<<N, 512>>>(src, pn, k, koffs[si]);
        } else {
            if (pn == HH) {
                // last scale: residual used directly
            } else {
                int outs = N*CC;
                if (k <= 4) k_ds_thread<<<(outs + 255)/256, 256>>>(src, pn, k);
                else        k_ds_warp<<<(outs*32 + 255)/256, 256>>>(src, pn, k);
            }
            const float* restp = (pn == HH) ? src : (const float*)restPtr;
            dim3 g((N + 127)/128, VOCABN/chunks[si]);
            k_argmax_big<<<g, 128>>>(restp, N, pnpn, chunks[si], koffs[si]);
        }
        k_upconv<<<dim3(16, 8), 512, CONV_SMEM>>>(f, cb, phiw, phib, out,
                                                  phiIdx[si], si, pn, koffs[si]);
    }
    k_final<<<1, 128>>>(out);
}

// round 17
// speedup vs baseline: 1.1429x; 1.1429x over previous
#include <cuda_runtime.h>

#define BB 8
#define CC 32
#define HH 64
#define VOCABN 4096
#define NELEM (BB*CC*HH*HH)   // 131072
#define NSCALE 7
#define NKEYS 43688           // sum of B*pn*pn over all scales

typedef unsigned long long ull;

// -------- scratch (static __device__, no allocations) --------
__device__ float g_cbn[VOCABN*CC];            // normalized codebook, PAIR-INTERLEAVED:
                                              // g_cbn[p*64 + 2*c + h] = cbn[2p+h][c]
__device__ float g_frest[NELEM];              // running residual
__device__ float g_rest[BB*CC*32*32];         // downsampled residual (pn=8..32)
__device__ float g_hup[NELEM];                // upsampled gathered codes
__device__ ull g_keys[NKEYS];                 // packed (sim,idx) keys, per-scale offsets
__device__ float g_partials[NSCALE*128];      // per-block loss partials

// -------- f32x2 packed math (sm_100+) --------
__device__ __forceinline__ ull fma2(ull a, ull b, ull c) {
    ull d; asm("fma.rn.f32x2 %0, %1, %2, %3;" : "=l"(d) : "l"(a), "l"(b), "l"(c)); return d;
}
__device__ __forceinline__ ull add2(ull a, ull b) {
    ull d; asm("add.rn.f32x2 %0, %1, %2;" : "=l"(d) : "l"(a), "l"(b)); return d;
}
__device__ __forceinline__ ull pack2(float lo, float hi) {
    ull d; asm("mov.b64 %0, {%1, %2};" : "=l"(d) : "f"(lo), "f"(hi)); return d;
}
__device__ __forceinline__ void unpack2(ull v, float& lo, float& hi) {
    asm("mov.b64 {%0, %1}, %2;" : "=f"(lo), "=f"(hi) : "l"(v));
}

__device__ __forceinline__ unsigned f2ord(float f) {
    unsigned u = __float_as_uint(f);
    return (u & 0x80000000u) ? ~u : (u | 0x80000000u);
}

// -------- codebook row-normalize -> pair-interleaved layout --------
__global__ void k_cbn(const float* __restrict__ cb) {
    int row = (blockIdx.x*blockDim.x + threadIdx.x) >> 5;
    int lane = threadIdx.x & 31;
    if (row >= VOCABN) return;
    float v = cb[row*CC + lane];
    float s = v*v;
    #pragma unroll
    for (int o = 16; o; o >>= 1) s += __shfl_xor_sync(0xffffffffu, s, o);
    int p = row >> 1, h = row & 1;
    g_cbn[p*64 + 2*lane + h] = v / sqrtf(s);
}

// -------- area downsample, thread per output (k <= 4) --------
__global__ void k_ds_thread(const float* __restrict__ src, int pn, int k) {
    int i = blockIdx.x*blockDim.x + threadIdx.x;
    int total = BB*CC*pn*pn;
    if (i >= total) return;
    int q = i % pn; int p = (i/pn) % pn; int bc = i/(pn*pn);
    const float* s = src + bc*HH*HH + p*k*HH + q*k;
    float acc = 0.f;
    for (int yy = 0; yy < k; yy++)
        for (int xx = 0; xx < k; xx++) acc += s[yy*HH + xx];
    g_rest[i] = acc * (1.f/(float)(k*k));
}

// -------- area downsample, warp per output (k >= 8) --------
__global__ void k_ds_warp(const float* __restrict__ src, int pn, int k) {
    int gw = (blockIdx.x*blockDim.x + threadIdx.x) >> 5;
    int lane = threadIdx.x & 31;
    int total = BB*CC*pn*pn;
    if (gw >= total) return;
    int q = gw % pn; int p = (gw/pn) % pn; int bc = gw/(pn*pn);
    const float* s = src + bc*HH*HH + p*k*HH + q*k;
    int kk = k*k;
    float acc = 0.f;
    for (int t = lane; t < kk; t += 32) acc += s[(t/k)*HH + (t % k)];
    #pragma unroll
    for (int o = 16; o; o >>= 1) acc += __shfl_xor_sync(0xffffffffu, acc, o);
    if (lane == 0) g_rest[gw] = acc * (1.f/(float)kk);
}

// -------- pair dot-product core: 32 channels vs packed code pair --------
__device__ __forceinline__ void pair_sim(const ull* __restrict__ vd,
                                         const float* __restrict__ pairrow,
                                         float& lo, float& hi) {
    const ulonglong2* row2 = (const ulonglong2*)pairrow;
    ull a0 = 0ull, a1 = 0ull, a2 = 0ull, a3 = 0ull;
    #pragma unroll
    for (int cc = 0; cc < 8; cc++) {
        ulonglong2 r0 = row2[2*cc];
        ulonglong2 r1 = row2[2*cc+1];
        a0 = fma2(vd[4*cc+0], r0.x, a0);
        a1 = fma2(vd[4*cc+1], r0.y, a1);
        a2 = fma2(vd[4*cc+2], r1.x, a2);
        a3 = fma2(vd[4*cc+3], r1.y, a3);
    }
    ull s = add2(add2(a0, a1), add2(a2, a3));
    unpack2(s, lo, hi);
}

// -------- argmax with FUSED area-downsample, CODE-SPLIT x4 (pn<=4) --------
// grid (N, 4): blockIdx.y selects 512 of the 2048 code pairs; each thread
// scans exactly ONE pair. Downsample recomputed per split (bit-identical,
// L2-resident reads). Result merged via atomicMax on pre-zeroed keys.
__global__ void k_argmax_small(const float* __restrict__ src, int pn, int k, int koff) {
    __shared__ float psum[512];
    __shared__ float vsh[CC];
    __shared__ ull kred[512];
    int n = blockIdx.x;
    int tid = threadIdx.x;
    int pnpn = pn*pn;
    int b = n / pnpn, r = n % pnpn;
    int p = r / pn, q = r % pn;
    // fused patch mean: channel c = tid>>4, 16 partial-sum threads per channel
    {
        int c = tid >> 4, sub = tid & 15;
        const float* sp = src + (b*CC + c)*HH*HH + p*k*HH + q*k;
        int kk = k*k;
        float a = 0.f;
        for (int t = sub; t < kk; t += 16) a += sp[(t/k)*HH + (t%k)];
        psum[tid] = a;
        __syncthreads();
        if (sub == 0) {
            float s = 0.f;
            #pragma unroll
            for (int u = 0; u < 16; u++) s += psum[(c<<4) + u];
            vsh[c] = s * (1.f/(float)kk);
        }
        __syncthreads();
    }
    ull vd[CC];
    #pragma unroll
    for (int c = 0; c < CC; c++) { float v = vsh[c]; vd[c] = pack2(v, v); }
    // one code pair per thread
    int pr = blockIdx.y*512 + tid;
    float lo, hi;
    pair_sim(vd, g_cbn + pr*64, lo, hi);
    float best = lo; int bidx = 2*pr;
    if (hi > best) { best = hi; bidx = 2*pr + 1; }
    kred[tid] = ((ull)f2ord(best) << 32) | (ull)(0xFFFFFFFFu - (unsigned)bidx);
    __syncthreads();
    #pragma unroll
    for (int s = 256; s > 0; s >>= 1) {
        if (tid < s) { ull o = kred[tid+s]; if (o > kred[tid]) kred[tid] = o; }
        __syncthreads();
    }
    if (tid == 0) atomicMax(g_keys + koff + n, kred[0]);
}

// -------- argmax, thread per vector, codes split across blockIdx.y --------
// REQUIREMENT: chunk must be a multiple of 256 (full tiles only).
__global__ void k_argmax_big(const float* __restrict__ rest, int N, int pnpn,
                             int chunk, int koff) {
    __shared__ float scb[256*CC];  // 32 KB tile: 128 pairs x 64 floats
    int n = blockIdx.x*128 + threadIdx.x;
    int c0 = blockIdx.y * chunk;
    ull vd[CC];
    bool active = (n < N);
    if (active) {
        int b = n / pnpn, r = n % pnpn;
        const float* s = rest + b*CC*pnpn + r;
        #pragma unroll
        for (int c = 0; c < CC; c++) { float v = s[c*pnpn]; vd[c] = pack2(v, v); }
    } else {
        #pragma unroll
        for (int c = 0; c < CC; c++) vd[c] = 0ull;
    }
    float best = -1e30f; int bidx = 0;
    for (int t0 = 0; t0 < chunk; t0 += 256) {
        __syncthreads();
        const float4* src4 = (const float4*)(g_cbn + (c0 + t0)*CC);
        float4* dst4 = (float4*)scb;
        #pragma unroll 4
        for (int i = threadIdx.x; i < 256*8; i += 128) dst4[i] = src4[i];
        __syncthreads();
        #pragma unroll 4
        for (int j2 = 0; j2 < 128; j2++) {
            float lo, hi;
            pair_sim(vd, scb + j2*64, lo, hi);
            int code = c0 + t0 + 2*j2;
            if (lo > best) { best = lo; bidx = code; }
            if (hi > best) { best = hi; bidx = code + 1; }
        }
    }
    if (active) {
        ull key = ((ull)f2ord(best) << 32) | (ull)(0xFFFFFFFFu - (unsigned)bidx);
        atomicMax(g_keys + koff + n, key);
    }
}

// -------- bicubic weight (PyTorch A=-0.75) --------
__device__ __forceinline__ float cubicw(float t) {
    t = fabsf(t);
    float t2 = t*t, t3 = t2*t;
    if (t <= 1.f) return 1.25f*t3 - 2.25f*t2 + 1.f;
    if (t < 2.f)  return -0.75f*t3 + 3.75f*t2 - 6.f*t + 3.f;
    return 0.f;
}

// -------- gather + bicubic upsample (or direct gather for pn==64) --------
// MLP-batched gathers + smem transpose for coalesced g_hup stores.
__global__ __launch_bounds__(256) void k_up(const float* __restrict__ cb, int pn, int koff) {
    __shared__ float swx[8][4];
    __shared__ int   spx[8][4];
    __shared__ float swy[4];
    __shared__ int   spy[4];
    __shared__ float st[8][33];
    int c = threadIdx.x;                    // 0..31 (channel)
    int tyi = threadIdx.y;                  // 0..7
    int X0 = blockIdx.x*8;
    int X = X0 + tyi;                       // 0..63
    int Y = blockIdx.y;                     // 0..63
    int b = blockIdx.z;                     // 0..7
    int tid = tyi*32 + c;
    const ull* keys = g_keys + koff;
    float out;
    if (pn == HH) {
        int n = (b*HH + Y)*HH + X;
        int idx = (int)(0xFFFFFFFFu - (unsigned)(keys[n] & 0xFFFFFFFFull));
        out = cb[idx*CC + c];
    } else {
        if (tid < 9) {
            float scale = (float)pn / (float)HH;
            int pos = (tid < 8) ? (X0 + tid) : Y;
            float fz = (pos + 0.5f)*scale - 0.5f;
            int z0 = (int)floorf(fz);
            #pragma unroll
            for (int t = 0; t < 4; t++) {
                float w = cubicw(fz - (float)(z0 - 1 + t));
                int pz = min(max(z0 - 1 + t, 0), pn - 1);
                if (tid < 8) { swx[tid][t] = w; spx[tid][t] = pz; }
                else         { swy[t] = w;     spy[t] = pz; }
            }
        }
        __syncthreads();
        // batch all 16 gathers (independent -> MLP 16)
        int nb = b*pn*pn;
        float vals[16];
        #pragma unroll
        for (int t = 0; t < 16; t++) {
            int py = spy[t >> 2], px = spx[tyi][t & 3];
            int idx = (int)(0xFFFFFFFFu - (unsigned)(keys[nb + py*pn + px] & 0xFFFFFFFFull));
            vals[t] = cb[idx*CC + c];
        }
        float acc = 0.f;
        #pragma unroll
        for (int t2 = 0; t2 < 4; t2++) {
            float rowacc = vals[t2*4+0]*swx[tyi][0] + vals[t2*4+1]*swx[tyi][1]
                         + vals[t2*4+2]*swx[tyi][2] + vals[t2*4+3]*swx[tyi][3];
            acc += swy[t2]*rowacc;
        }
        out = acc;
    }
    st[tyi][c] = out;
    __syncthreads();
    // coalesced store: warp writes 4 channels x 8 consecutive X
    int c2 = tid >> 3, x2 = tid & 7;
    g_hup[(b*CC + c2)*HH*HH + Y*HH + X0 + x2] = st[x2][c2];
}

// -------- conv3x3 + Phi blend + update + loss partial --------
// WARP-PER-OC-PAIR layout: 16 warps = 16 oc-pairs; thread = 2y x 4x quad.
// PY-SPLIT mainloop (r15 measured state).
#define CONV_SMEM ((32*6*66 + 16*32*10*2 + 32 + 512)*4)

__global__ __launch_bounds__(512, 1) void k_conv(
        const float* __restrict__ f, const float* __restrict__ phi_w,
        const float* __restrict__ phi_b, float* __restrict__ fhat,
        int kphi, int si) {
    extern __shared__ float sh[];
    float* tile  = sh;                    // 32*6*66 = 12672 floats
    float* wsh2f = tile + 32*6*66;        // 16 P * 32 ic * 10 ull = 10240 floats
    float* bsh   = wsh2f + 16*32*10*2;    // 32
    float* red   = bsh + 32;              // 512
    int tid = threadIdx.x;                // 0..511 (flat block)
    int P    = tid >> 5;                  // warp id = oc-pair 0..15
    int lane = tid & 31;
    int r = lane >> 4;                    // row-pair: rows 2r, 2r+1 of the 4-row stripe
    int q = lane & 15;                    // col quad: cols 4q..4q+3
    int y0 = blockIdx.x*4;
    int b  = blockIdx.y;

    // interleave weights (all 32 oc): wsh2f[((P*32+ic)*10 + t)*2 + h] = w[2P+h][ic][t]
    const float* wsrc = phi_w + (size_t)(kphi*32)*32*9;
    for (int i = tid; i < 16*32*9; i += 512) {
        int Pp = i / 288; int rem = i % 288;
        int ic = rem / 9; int t = rem % 9;
        int dst = ((Pp*32 + ic)*10 + t)*2;
        wsh2f[dst]     = wsrc[(2*Pp)*288 + rem];
        wsh2f[dst + 1] = wsrc[(2*Pp + 1)*288 + rem];
    }
    if (tid < 32) bsh[tid] = phi_b[kphi*32 + tid];

    // vectorized tile load: one thread per (ic,yy) row, 16x float4 + zero edges
    for (int rr = tid; rr < 32*6; rr += 512) {
        int ic = rr / 6, yy = rr % 6;
        int gy = y0 - 1 + yy;
        float* trow = tile + rr*66;
        if ((unsigned)gy < 64u) {
            const float* g = g_hup + ((b*CC + ic)*HH + gy)*HH;
            trow[0] = 0.f; trow[65] = 0.f;
            #pragma unroll
            for (int kq = 0; kq < 16; kq++) {
                float4 v = *(const float4*)(g + 4*kq);
                trow[1 + 4*kq] = v.x; trow[2 + 4*kq] = v.y;
                trow[3 + 4*kq] = v.z; trow[4 + 4*kq] = v.w;
            }
        } else {
            #pragma unroll 6
            for (int xx = 0; xx < 66; xx++) trow[xx] = 0.f;
        }
    }
    __syncthreads();

    const ull* wsh2 = (const ull*)wsh2f;
    ull acc2[8];   // [py*4+px], lo = oc 2P, hi = oc 2P+1
    #pragma unroll
    for (int i = 0; i < 8; i++) acc2[i] = 0ull;

    for (int ic = 0; ic < 32; ic++) {
        const ull* w = wsh2 + (P*32 + ic)*10;
        ulonglong2 w01 = *(const ulonglong2*)(w);
        ulonglong2 w23 = *(const ulonglong2*)(w + 2);
        ulonglong2 w45 = *(const ulonglong2*)(w + 4);
        ulonglong2 w67 = *(const ulonglong2*)(w + 6);
        ull w8 = w[8];
        #pragma unroll
        for (int py = 0; py < 2; py++) {
            const float2* tb2 = (const float2*)(tile + (ic*6 + 2*r + py)*66 + 4*q);
            ull t[3][6];
            #pragma unroll
            for (int yy = 0; yy < 3; yy++) {
                float2 f0 = tb2[yy*33 + 0];
                float2 f1 = tb2[yy*33 + 1];
                float2 f2 = tb2[yy*33 + 2];
                t[yy][0] = pack2(f0.x, f0.x); t[yy][1] = pack2(f0.y, f0.y);
                t[yy][2] = pack2(f1.x, f1.x); t[yy][3] = pack2(f1.y, f1.y);
                t[yy][4] = pack2(f2.x, f2.x); t[yy][5] = pack2(f2.y, f2.y);
            }
            #pragma unroll
            for (int px = 0; px < 4; px++) {
                ull a = acc2[py*4 + px];
                a = fma2(t[0][px+0], w01.x, a);
                a = fma2(t[0][px+1], w01.y, a);
                a = fma2(t[0][px+2], w23.x, a);
                a = fma2(t[1][px+0], w23.y, a);
                a = fma2(t[1][px+1], w45.x, a);
                a = fma2(t[1][px+2], w45.y, a);
                a = fma2(t[2][px+0], w67.x, a);
                a = fma2(t[2][px+1], w67.y, a);
                a = fma2(t[2][px+2], w8,    a);
                acc2[py*4 + px] = a;
            }
        }
    }

    float ss = 0.f;
    #pragma unroll
    for (int py = 0; py < 2; py++) {
        int yrow = 2*r + py;          // 0..3 within stripe
        int y = y0 + yrow;
        #pragma unroll
        for (int px = 0; px < 4; px++) {
            int x = 4*q + px;
            float aLo, aHi;
            unpack2(acc2[py*4 + px], aLo, aHi);
            #pragma unroll
            for (int hh = 0; hh < 2; hh++) {
                int oc = 2*P + hh;
                float a = hh ? aHi : aLo;
                float hid = tile[(oc*6 + yrow + 1)*66 + (x + 1)];
                float hp = 0.5f*hid + 0.5f*(a + bsh[oc]);
                int gi = ((b*CC + oc)*HH + y)*HH + x;
                float fv = f[gi];
                float fh = (si == 0 ? 0.f : fhat[gi]) + hp;
                fhat[gi] = fh;
                g_frest[gi] = fv - fh;
                float d = fh - fv;
                ss += d*d;
            }
        }
    }

    red[tid] = ss;
    __syncthreads();
    #pragma unroll
    for (int s = 256; s > 0; s >>= 1) {
        if (tid < s) red[tid] += red[tid + s];
        __syncthreads();
    }
    if (tid == 0) {
        int bl = blockIdx.y*16 + blockIdx.x;   // 0..127
        g_partials[si*128 + bl] = red[0];
    }
}

// -------- final loss reduce (deterministic fixed order) --------
__global__ void k_final(float* __restrict__ out) {
    __shared__ float red[128];
    int tid = threadIdx.x;
    float s = 0.f;
    for (int i = tid; i < NSCALE*128; i += 128) s += g_partials[i];
    red[tid] = s;
    __syncthreads();
    #pragma unroll
    for (int st = 64; st > 0; st >>= 1) {
        if (tid < st) red[tid] += red[tid + st];
        __syncthreads();
    }
    if (tid == 0) {
        float T = red[0];
        out[NELEM]     = T / (7.f * (float)NELEM);
        out[NELEM + 1] = 0.25f * T / (float)NELEM;
    }
}

// -------- host --------
extern "C" void kernel_launch(void* const* d_in, const int* in_sizes, int n_in,
                              void* d_out, int out_size) {
    const float* f    = (const float*)d_in[0];
    const float* cb   = (const float*)d_in[1];
    const float* phiw = (const float*)d_in[2];
    const float* phib = (const float*)d_in[3];
    float* out = (float*)d_out;

    cudaFuncSetAttribute(k_conv, cudaFuncAttributeMaxDynamicSharedMemorySize, CONV_SMEM);

    void *keysPtr = nullptr, *frestPtr = nullptr, *restPtr = nullptr;
    cudaGetSymbolAddress(&keysPtr, g_keys);
    cudaGetSymbolAddress(&frestPtr, g_frest);
    cudaGetSymbolAddress(&restPtr, g_rest);

    // one upfront zero of the whole key buffer (covers all atomic-merged scales)
    cudaMemsetAsync(keysPtr, 0, (size_t)NKEYS*sizeof(ull));
    k_cbn<<<(VOCABN*32 + 255)/256, 256>>>(cb);

    const int pns[NSCALE]    = {1, 2, 4, 8, 16, 32, 64};
    // PHI ticks in float64: si=3 (key 0.5) resolves to phi index 2 (fp tie-break), NOT 1.
    const int phiIdx[NSCALE] = {0, 0, 1, 2, 2, 3, 3};
    // chunks MUST be multiples of 256 (k_argmax_big scans full 256-code tiles).
    const int chunks[NSCALE] = {0, 0, 0, 256, 256, 512, 2048};
    // per-scale key offsets: prefix sums of N = 8*pn*pn
    const int koffs[NSCALE]  = {0, 8, 40, 168, 680, 2728, 10920};

    for (int si = 0; si < NSCALE; si++) {
        int pn = pns[si]; int pnpn = pn*pn; int N = BB*pnpn; int k = HH/pn;
        const float* src = (si == 0) ? f : (const float*)frestPtr;

        if (pn <= 4) {
            // fused downsample + argmax, 4-way code split, atomicMax merge
            k_argmax_small<<<dim3(N, 4), 512>>>(src, pn, k, koffs[si]);
        } else {
            if (pn == HH) {
                // last scale: residual used directly
            } else {
                int outs = N*CC;
                if (k <= 4) k_ds_thread<<<(outs + 255)/256, 256>>>(src, pn, k);
                else        k_ds_warp<<<(outs*32 + 255)/256, 256>>>(src, pn, k);
            }
            const float* restp = (pn == HH) ? src : (const float*)restPtr;
            dim3 g((N + 127)/128, VOCABN/chunks[si]);
            k_argmax_big<<<g, 128>>>(restp, N, pnpn, chunks[si], koffs[si]);
        }
        k_up<<<dim3(8, 64, 8), dim3(32, 8)>>>(cb, pn, koffs[si]);
        k_conv<<<dim3(16, 8), 512, CONV_SMEM>>>(f, phiw, phib, out, phiIdx[si], si);
    }
    k_final<<<1, 128>>>(out);
}